// round 9
// baseline (speedup 1.0000x reference)
#include <cuda_runtime.h>
#include <math.h>

typedef unsigned long long u64;
typedef unsigned int u32;

// ---------------------------------------------------------------- constants
#define D_MODEL 512
#define D_INNER 512
#define D_STATE 16
#define DT_RANK 32
#define BB      4
#define LL      2048
#define MTOK    (BB*LL)       // 8192 tokens
#define CH_T    64            // scan chunk length
#define NCHUNK  (LL/CH_T)     // 32 chunks

// ---------------------------------------------------------------- scratch
__device__ __align__(16) float g_hstats[BB*D_MODEL];
__device__ __align__(16) float g_h    [MTOK*D_MODEL];
__device__ __align__(16) float g_xn   [MTOK*D_MODEL];
__device__ __align__(16) float g_xz   [MTOK*2*D_INNER];
__device__ __align__(16) float g_u    [MTOK*D_INNER];
__device__ __align__(16) float g_xdbc [MTOK*64];
__device__ __align__(16) float g_delta[MTOK*D_INNER];
__device__ __align__(16) float g_q    [BB*D_INNER*NCHUNK*D_STATE];
__device__ __align__(16) float g_dsum [BB*D_INNER*NCHUNK];
__device__ __align__(16) float g_hinit[BB*D_INNER*NCHUNK*D_STATE];
__device__ __align__(16) float g_y    [MTOK*D_INNER];

// ---------------------------------------------------------------- tf32 helpers
__device__ __forceinline__ u32 f2tf32(float f) {
    u32 r;
    asm("cvt.rna.tf32.f32 %0, %1;" : "=r"(r) : "f"(f));
    return r;
}
__device__ __forceinline__ void mma_tf32_v(float* d, u32 a0, u32 a1, u32 a2, u32 a3,
                                           u32 b0, u32 b1) {
    asm volatile(
        "mma.sync.aligned.m16n8k8.row.col.f32.tf32.tf32.f32 "
        "{%0,%1,%2,%3}, {%4,%5,%6,%7}, {%8,%9}, {%0,%1,%2,%3};"
        : "+f"(d[0]), "+f"(d[1]), "+f"(d[2]), "+f"(d[3])
        : "r"(a0), "r"(a1), "r"(a2), "r"(a3), "r"(b0), "r"(b1));
}

// ---------------------------------------------------------------- TF32 GEMM (NT)
// C[M,N] = A[M,K] @ B[N,K]^T ; tf32 inputs, fp32 accumulate.
// Block 128x128, BK=32, 256 threads = 8 warps (4 M x 2 N), warp tile 32x64.
// Smem stores k permuted: col perm(k) = (k&3)*8 + (k>>2). A thread's 8 needed
// k-values (stride 4) are then contiguous -> uint4 fragment loads (LDS.128).
// EPI: 0 = none, 1 = relu(acc + bias[(m>>11)*512 + n])
template<int EPI>
__global__ __launch_bounds__(256)
void tf32gemm_nt(const float* __restrict__ A, const float* __restrict__ B,
                 float* __restrict__ C, int M, int N, int K,
                 int lda, int ldb, int ldc, const float* __restrict__ bias)
{
    constexpr int BM = 128, BN = 128, BK = 32, LDS_S = BK + 4;  // pad->conflict-free reads
    __shared__ u32 As[BM][LDS_S];
    __shared__ u32 Bs[BN][LDS_S];

    const int tid  = threadIdx.x;
    const int lane = tid & 31;
    const int warp = tid >> 5;
    const int gid  = lane >> 2;      // 0..7
    const int tig  = lane & 3;       // 0..3
    const int wm   = warp & 3;       // 4 warps along M
    const int wn   = warp >> 2;      // 2 warps along N
    const int m0   = blockIdx.y * BM;
    const int n0   = blockIdx.x * BN;

    float acc[2][8][4];
#pragma unroll
    for (int i = 0; i < 2; i++)
#pragma unroll
        for (int j = 0; j < 8; j++)
#pragma unroll
            for (int r = 0; r < 4; r++) acc[i][j][r] = 0.f;

    // tile loader: 128 rows x 32 k; each thread: float4 at k-offset lc, 4 row-passes
    const int lr = tid >> 3;         // row within pass
    const int lc = (tid & 7) * 4;    // k offset (consecutive 4 k)
    const int lq = tid & 7;          // = lc>>2 : permuted sub-column

    for (int k0 = 0; k0 < K; k0 += BK) {
#pragma unroll
        for (int p = 0; p < 4; p++) {
            int r = lr + p * 32;
            float4 va = *(const float4*)(A + (size_t)(m0 + r) * lda + k0 + lc);
            As[r][lq     ] = f2tf32(va.x);   // k = lc+0 -> col 0*8 + q
            As[r][lq + 8 ] = f2tf32(va.y);   // k = lc+1 -> col 8 + q
            As[r][lq + 16] = f2tf32(va.z);
            As[r][lq + 24] = f2tf32(va.w);
            float4 vb = *(const float4*)(B + (size_t)(n0 + r) * ldb + k0 + lc);
            Bs[r][lq     ] = f2tf32(vb.x);
            Bs[r][lq + 8 ] = f2tf32(vb.y);
            Bs[r][lq + 16] = f2tf32(vb.z);
            Bs[r][lq + 24] = f2tf32(vb.w);
        }
        __syncthreads();

        // two half-BK groups; each uint4 covers 2 k-atoms (even: .x/.y, odd: .z/.w)
#pragma unroll
        for (int kg = 0; kg < 2; kg++) {
            const int fc = tig * 8 + kg * 4;     // fragment column
            u32 ae[2][4], ao[2][4];
#pragma unroll
            for (int i = 0; i < 2; i++) {
                const int mr = wm * 32 + i * 16;
                uint4 lo = *(const uint4*)&As[mr + gid    ][fc];
                uint4 hi = *(const uint4*)&As[mr + gid + 8][fc];
                ae[i][0] = lo.x; ae[i][1] = hi.x; ae[i][2] = lo.y; ae[i][3] = hi.y;
                ao[i][0] = lo.z; ao[i][1] = hi.z; ao[i][2] = lo.w; ao[i][3] = hi.w;
            }
#pragma unroll
            for (int j = 0; j < 8; j++) {
                const int nr = wn * 64 + j * 8;
                uint4 vb = *(const uint4*)&Bs[nr + gid][fc];
                mma_tf32_v(acc[0][j], ae[0][0], ae[0][1], ae[0][2], ae[0][3], vb.x, vb.y);
                mma_tf32_v(acc[1][j], ae[1][0], ae[1][1], ae[1][2], ae[1][3], vb.x, vb.y);
                mma_tf32_v(acc[0][j], ao[0][0], ao[0][1], ao[0][2], ao[0][3], vb.z, vb.w);
                mma_tf32_v(acc[1][j], ao[1][0], ao[1][1], ao[1][2], ao[1][3], vb.z, vb.w);
            }
        }
        __syncthreads();
    }

    // epilogue: c0=(gid, 2t), c1=(gid, 2t+1), c2=(gid+8, 2t), c3=(gid+8, 2t+1)
#pragma unroll
    for (int i = 0; i < 2; i++) {
        const int mlo = m0 + wm * 32 + i * 16 + gid;
        const int mhi = mlo + 8;
#pragma unroll
        for (int j = 0; j < 8; j++) {
            const int n = n0 + wn * 64 + j * 8 + tig * 2;
            float2 f01 = make_float2(acc[i][j][0], acc[i][j][1]);
            float2 f23 = make_float2(acc[i][j][2], acc[i][j][3]);
            if (EPI == 1) {
                const float* blo = bias + (mlo >> 11) * D_MODEL;
                const float* bhi = bias + (mhi >> 11) * D_MODEL;
                f01.x = fmaxf(f01.x + blo[n], 0.f); f01.y = fmaxf(f01.y + blo[n + 1], 0.f);
                f23.x = fmaxf(f23.x + bhi[n], 0.f); f23.y = fmaxf(f23.y + bhi[n + 1], 0.f);
            }
            *(float2*)&C[(size_t)mlo * ldc + n] = f01;
            *(float2*)&C[(size_t)mhi * ldc + n] = f23;
        }
    }
}

// ---------------------------------------------------------------- fp32 SGEMM (NT) for small GEMMs
template<int BM, int BN, int TM, int TN, int EPI>
__global__ __launch_bounds__(256)
void sgemm_nt(const float* __restrict__ A, const float* __restrict__ B,
              float* __restrict__ C, int M, int N, int K,
              int lda, int ldb, int ldc, const float* __restrict__ bias)
{
    constexpr int BK = 16;
    __shared__ float As[BK][BM + 4];
    __shared__ float Bs[BK][BN + 4];

    const int tid = threadIdx.x;
    const int tx  = tid & 15;
    const int ty  = tid >> 4;
    const int m0  = blockIdx.y * BM;
    const int n0  = blockIdx.x * BN;

    float acc[TM][TN];
#pragma unroll
    for (int i = 0; i < TM; i++)
#pragma unroll
        for (int j = 0; j < TN; j++) acc[i][j] = 0.f;

    const float* Ab = A + (size_t)m0 * lda;
    const float* Bb = B + (size_t)n0 * ldb;

    for (int k0 = 0; k0 < K; k0 += BK) {
#pragma unroll
        for (int i = 0; i < (BM * BK) / 1024; i++) {
            int t = tid + i * 256;
            int r = t >> 2, cq = t & 3;
            float4 v = *(const float4*)(Ab + (size_t)r * lda + k0 + cq * 4);
            As[cq*4+0][r] = v.x; As[cq*4+1][r] = v.y;
            As[cq*4+2][r] = v.z; As[cq*4+3][r] = v.w;
        }
#pragma unroll
        for (int i = 0; i < (BN * BK) / 1024; i++) {
            int t = tid + i * 256;
            int r = t >> 2, cq = t & 3;
            float4 v = *(const float4*)(Bb + (size_t)r * ldb + k0 + cq * 4);
            Bs[cq*4+0][r] = v.x; Bs[cq*4+1][r] = v.y;
            Bs[cq*4+2][r] = v.z; Bs[cq*4+3][r] = v.w;
        }
        __syncthreads();

#pragma unroll
        for (int k = 0; k < BK; k++) {
            float a[TM], b[TN];
#pragma unroll
            for (int i = 0; i < TM; i += 4) {
                float4 v = *(const float4*)&As[k][ty * TM + i];
                a[i] = v.x; a[i+1] = v.y; a[i+2] = v.z; a[i+3] = v.w;
            }
#pragma unroll
            for (int j = 0; j < TN; j += 4) {
                float4 v = *(const float4*)&Bs[k][tx * TN + j];
                b[j] = v.x; b[j+1] = v.y; b[j+2] = v.z; b[j+3] = v.w;
            }
#pragma unroll
            for (int i = 0; i < TM; i++)
#pragma unroll
                for (int j = 0; j < TN; j++)
                    acc[i][j] = fmaf(a[i], b[j], acc[i][j]);
        }
        __syncthreads();
    }

#pragma unroll
    for (int i = 0; i < TM; i++) {
        int m = m0 + ty * TM + i;
#pragma unroll
        for (int j = 0; j < TN; j++) {
            int n = n0 + tx * TN + j;
            float v = acc[i][j];
            if (EPI == 2) {          // dt_proj: + bias, softplus
                v += bias[n];
                v = (v > 20.f) ? v : log1pf(expf(v));
            }
            C[(size_t)m * ldc + n] = v;
        }
    }
}

// ---------------------------------------------------------------- hstats
__global__ void hstats_kernel(const float* __restrict__ gW1,
                              const float* __restrict__ gb1,
                              const float* __restrict__ xstat)
{
    int idx = blockIdx.x * blockDim.x + threadIdx.x;
    if (idx >= BB * D_MODEL) return;
    int b = idx >> 9, j = idx & 511;
    const float* w  = gW1 + (size_t)j * (2 * D_MODEL) + D_MODEL;
    const float* xs = xstat + b * D_MODEL;
    float s = gb1[j];
#pragma unroll 8
    for (int k = 0; k < D_MODEL; k++) s = fmaf(w[k], xs[k], s);
    g_hstats[idx] = s;
}

// ---------------------------------------------------------------- gate + LN
__global__ __launch_bounds__(256)
void gate_ln_kernel(const float* __restrict__ xsig, const float* __restrict__ xstat,
                    const float* __restrict__ h,    const float* __restrict__ gW2,
                    const float* __restrict__ gb2,  const float* __restrict__ lng,
                    const float* __restrict__ lnb,  float* __restrict__ xn)
{
    const int t = blockIdx.x;
    const int b = t >> 11;
    const int tid = threadIdx.x;
    const int d0 = tid, d1 = tid + 256;

    __shared__ float sred[8];
    __shared__ float sred2[8][2];
    __shared__ float sbc[2];

    const float* hr = h + (size_t)t * D_MODEL;
    float p = hr[d0] * gW2[d0] + hr[d1] * gW2[d1];
#pragma unroll
    for (int o = 16; o > 0; o >>= 1) p += __shfl_xor_sync(0xffffffffu, p, o);
    if ((tid & 31) == 0) sred[tid >> 5] = p;
    __syncthreads();
    if (tid == 0) {
        float s = 0.f;
        for (int w = 0; w < 8; w++) s += sred[w];
        sbc[0] = 1.f / (1.f + expf(-(s + gb2[0])));
    }
    __syncthreads();
    const float gate = sbc[0];

    float x0 = xsig[(size_t)t * D_MODEL + d0] + gate * xstat[b * D_MODEL + d0];
    float x1 = xsig[(size_t)t * D_MODEL + d1] + gate * xstat[b * D_MODEL + d1];
    float s  = x0 + x1;
    float ss = x0 * x0 + x1 * x1;
#pragma unroll
    for (int o = 16; o > 0; o >>= 1) {
        s  += __shfl_xor_sync(0xffffffffu, s,  o);
        ss += __shfl_xor_sync(0xffffffffu, ss, o);
    }
    if ((tid & 31) == 0) { sred2[tid >> 5][0] = s; sred2[tid >> 5][1] = ss; }
    __syncthreads();
    if (tid == 0) {
        float S = 0.f, SS = 0.f;
        for (int w = 0; w < 8; w++) { S += sred2[w][0]; SS += sred2[w][1]; }
        float mu  = S * (1.f / D_MODEL);
        float var = SS * (1.f / D_MODEL) - mu * mu;
        sbc[0] = mu;
        sbc[1] = rsqrtf(var + 1e-5f);
    }
    __syncthreads();
    const float mu = sbc[0], rstd = sbc[1];
    xn[(size_t)t * D_MODEL + d0] = (x0 - mu) * rstd * lng[d0] + lnb[d0];
    xn[(size_t)t * D_MODEL + d1] = (x1 - mu) * rstd * lng[d1] + lnb[d1];
}

// ---------------------------------------------------------------- conv(k=2)+silu
__global__ void conv_silu_kernel(const float* __restrict__ xz,
                                 const float* __restrict__ conv_w,
                                 const float* __restrict__ conv_b,
                                 float* __restrict__ u)
{
    int idx = blockIdx.x * blockDim.x + threadIdx.x;
    if (idx >= MTOK * D_INNER) return;
    int d = idx & 511;
    int l = (idx >> 9) & (LL - 1);
    int t = idx >> 9;
    float ucur  = xz[(size_t)t * (2 * D_INNER) + d];
    float uprev = (l > 0) ? xz[(size_t)(t - 1) * (2 * D_INNER) + d] : 0.f;
    float v = conv_b[d] + conv_w[d * 2 + 0] * uprev + conv_w[d * 2 + 1] * ucur;
    float sg = 1.f / (1.f + __expf(-v));
    u[idx] = v * sg;
}

// ---------------------------------------------------------------- scan helpers
__device__ __forceinline__ bool load_aexp(const float* __restrict__ A_log,
                                          int d, float* aexp)
{
    bool fast = true;
#pragma unroll
    for (int n = 0; n < D_STATE; n++) {
        aexp[n] = expf(A_log[d * D_STATE + n]);
        if (fabsf(aexp[n] - (float)(n + 1)) > 1e-2f) fast = false;
    }
    return fast;
}

// ---- pass 1
__global__ __launch_bounds__(128)
void scan_c1(const float* __restrict__ xdbc, const float* __restrict__ delta,
             const float* __restrict__ u,    const float* __restrict__ A_log)
{
    const int d = blockIdx.x * 128 + threadIdx.x;
    const int c = blockIdx.y, b = blockIdx.z;

    __shared__ float sB[CH_T * D_STATE];
    for (int i = threadIdx.x; i < CH_T * D_STATE; i += 128) {
        int j = i >> 4, n = i & 15;
        sB[i] = xdbc[(size_t)(b * LL + c * CH_T + j) * 64 + DT_RANK + n];
    }
    __syncthreads();

    float aexp[D_STATE];
    const bool fast = load_aexp(A_log, d, aexp);

    float h[D_STATE];
#pragma unroll
    for (int n = 0; n < D_STATE; n++) h[n] = 0.f;
    float dsum = 0.f;

    const float* dp = delta + (size_t)(b * LL + c * CH_T) * D_INNER + d;
    const float* up = u     + (size_t)(b * LL + c * CH_T) * D_INNER + d;

    if (fast) {
        for (int j = 0; j < CH_T; j++) {
            float de = dp[j * D_INNER], uu = up[j * D_INNER];
            dsum += de;
            float du = de * uu;
            float r = __expf(-de), rp = r;
#pragma unroll
            for (int n = 0; n < D_STATE; n++) {
                h[n] = fmaf(rp, h[n], du * sB[j * D_STATE + n]);
                rp *= r;
            }
        }
    } else {
        for (int j = 0; j < CH_T; j++) {
            float de = dp[j * D_INNER], uu = up[j * D_INNER];
            dsum += de;
            float du = de * uu;
#pragma unroll
            for (int n = 0; n < D_STATE; n++)
                h[n] = fmaf(__expf(-de * aexp[n]), h[n], du * sB[j * D_STATE + n]);
        }
    }

    const size_t base = (size_t)(b * D_INNER + d) * NCHUNK + c;
#pragma unroll
    for (int n = 0; n < D_STATE; n++) g_q[base * D_STATE + n] = h[n];
    g_dsum[base] = dsum;
}

// ---- pass 2
__global__ void scan_c2(const float* __restrict__ A_log)
{
    int bd = blockIdx.x * blockDim.x + threadIdx.x;
    if (bd >= BB * D_INNER) return;
    int d = bd & 511;

    float aexp[D_STATE];
    const bool fast = load_aexp(A_log, d, aexp);

    float h[D_STATE];
#pragma unroll
    for (int n = 0; n < D_STATE; n++) h[n] = 0.f;

    for (int c = 0; c < NCHUNK; c++) {
        const size_t base = (size_t)bd * NCHUNK + c;
#pragma unroll
        for (int n = 0; n < D_STATE; n++) g_hinit[base * D_STATE + n] = h[n];
        float ds = g_dsum[base];
        if (fast) {
            float r = __expf(-ds), rp = r;
#pragma unroll
            for (int n = 0; n < D_STATE; n++) {
                h[n] = fmaf(rp, h[n], g_q[base * D_STATE + n]);
                rp *= r;
            }
        } else {
#pragma unroll
            for (int n = 0; n < D_STATE; n++)
                h[n] = fmaf(__expf(-ds * aexp[n]), h[n], g_q[base * D_STATE + n]);
        }
    }
}

// ---- pass 3
__global__ __launch_bounds__(128)
void scan_c3(const float* __restrict__ xdbc, const float* __restrict__ delta,
             const float* __restrict__ u,    const float* __restrict__ A_log,
             const float* __restrict__ Dp,   const float* __restrict__ xz,
             float* __restrict__ y)
{
    const int d = blockIdx.x * 128 + threadIdx.x;
    const int c = blockIdx.y, b = blockIdx.z;

    __shared__ float sB[CH_T * D_STATE];
    __shared__ float sC[CH_T * D_STATE];
    for (int i = threadIdx.x; i < CH_T * D_STATE; i += 128) {
        int j = i >> 4, n = i & 15;
        const float* row = xdbc + (size_t)(b * LL + c * CH_T + j) * 64;
        sB[i] = row[DT_RANK + n];
        sC[i] = row[DT_RANK + D_STATE + n];
    }
    __syncthreads();

    float aexp[D_STATE];
    const bool fast = load_aexp(A_log, d, aexp);

    const size_t base = (size_t)(b * D_INNER + d) * NCHUNK + c;
    float h[D_STATE];
#pragma unroll
    for (int n = 0; n < D_STATE; n++) h[n] = g_hinit[base * D_STATE + n];

    const float dpd = Dp[d];
    const float* dptr = delta + (size_t)(b * LL + c * CH_T) * D_INNER + d;
    const float* uptr = u     + (size_t)(b * LL + c * CH_T) * D_INNER + d;

    for (int j = 0; j < CH_T; j++) {
        float de = dptr[j * D_INNER], uu = uptr[j * D_INNER];
        float du = de * uu;
        float yv = 0.f;
        if (fast) {
            float r = __expf(-de), rp = r;
#pragma unroll
            for (int n = 0; n < D_STATE; n++) {
                h[n] = fmaf(rp, h[n], du * sB[j * D_STATE + n]);
                yv   = fmaf(h[n], sC[j * D_STATE + n], yv);
                rp *= r;
            }
        } else {
#pragma unroll
            for (int n = 0; n < D_STATE; n++) {
                h[n] = fmaf(__expf(-de * aexp[n]), h[n], du * sB[j * D_STATE + n]);
                yv   = fmaf(h[n], sC[j * D_STATE + n], yv);
            }
        }
        const int l = b * LL + c * CH_T + j;
        float z  = xz[(size_t)l * (2 * D_INNER) + D_INNER + d];
        float sg = 1.f / (1.f + __expf(-z));
        y[(size_t)l * D_INNER + d] = (yv + dpd * uu) * (z * sg);
    }
}

// ---------------------------------------------------------------- launch
static float* symaddr(const void* sym)
{
    void* p = nullptr;
    cudaGetSymbolAddress(&p, sym);
    return (float*)p;
}

extern "C" void kernel_launch(void* const* d_in, const int* in_sizes, int n_in,
                              void* d_out, int out_size)
{
    const float* x_signal  = (const float*)d_in[0];
    const float* x_stats   = (const float*)d_in[1];
    const float* gW1       = (const float*)d_in[2];
    const float* gb1       = (const float*)d_in[3];
    const float* gW2       = (const float*)d_in[4];
    const float* gb2       = (const float*)d_in[5];
    const float* ln_g      = (const float*)d_in[6];
    const float* ln_b      = (const float*)d_in[7];
    const float* in_proj_W = (const float*)d_in[8];
    const float* conv_w    = (const float*)d_in[9];
    const float* conv_b    = (const float*)d_in[10];
    const float* x_proj_W  = (const float*)d_in[11];
    const float* dt_proj_W = (const float*)d_in[12];
    const float* dt_proj_b = (const float*)d_in[13];
    const float* A_log     = (const float*)d_in[14];
    const float* Dp        = (const float*)d_in[15];
    const float* out_proj_W= (const float*)d_in[16];
    float* out = (float*)d_out;

    float* p_hstats = symaddr(g_hstats);
    float* p_h      = symaddr(g_h);
    float* p_xn     = symaddr(g_xn);
    float* p_xz     = symaddr(g_xz);
    float* p_u      = symaddr(g_u);
    float* p_xdbc   = symaddr(g_xdbc);
    float* p_delta  = symaddr(g_delta);
    float* p_y      = symaddr(g_y);

    const int M = MTOK;

    // 1) per-batch half of the gate MLP (x_stats is broadcast over L)
    hstats_kernel<<<8, 256>>>(gW1, gb1, x_stats);

    // 2) GEMM1 (tf32): H = relu(X @ W1a^T + hstats[b])
    tf32gemm_nt<1><<<dim3(D_MODEL/128, M/128), 256>>>(
        x_signal, gW1, p_h, M, D_MODEL, D_MODEL, D_MODEL, 2*D_MODEL, D_MODEL, p_hstats);

    // 3) gate scalar + residual + LayerNorm
    gate_ln_kernel<<<M, 256>>>(x_signal, x_stats, p_h, gW2, gb2, ln_g, ln_b, p_xn);

    // 4) GEMM2 (tf32): XZ = XN @ in_proj_W^T   (N = 1024)
    tf32gemm_nt<0><<<dim3(1024/128, M/128), 256>>>(
        p_xn, in_proj_W, p_xz, M, 2*D_INNER, D_MODEL, D_MODEL, D_MODEL, 2*D_INNER, nullptr);

    // 5) causal conv (k=2) + silu -> u
    conv_silu_kernel<<<(M*D_INNER)/256, 256>>>(p_xz, conv_w, conv_b, p_u);

    // 6) GEMM3 (fp32): XDBC = U @ x_proj_W^T   (N = 64)
    sgemm_nt<64,64,4,4,0><<<dim3(1, M/64), 256>>>(
        p_u, x_proj_W, p_xdbc, M, 64, D_INNER, D_INNER, D_INNER, 64, nullptr);

    // 7) GEMM4 (fp32): delta = softplus(XDBC[:, :32] @ dt_proj_W^T + dt_bias)
    sgemm_nt<128,128,8,8,2><<<dim3(D_INNER/128, M/128), 256>>>(
        p_xdbc, dt_proj_W, p_delta, M, D_INNER, DT_RANK, 64, DT_RANK, D_INNER, dt_proj_b);

    // 8-10) chunked selective scan
    scan_c1<<<dim3(D_INNER/128, NCHUNK, BB), 128>>>(p_xdbc, p_delta, p_u, A_log);
    scan_c2<<<16, 128>>>(A_log);
    scan_c3<<<dim3(D_INNER/128, NCHUNK, BB), 128>>>(p_xdbc, p_delta, p_u, A_log, Dp, p_xz, p_y);

    // 11) GEMM5 (tf32): out = Y @ out_proj_W^T
    tf32gemm_nt<0><<<dim3(D_MODEL/128, M/128), 256>>>(
        p_y, out_proj_W, out, M, D_MODEL, D_INNER, D_INNER, D_INNER, D_MODEL, nullptr);
}

// round 11
// speedup vs baseline: 1.1739x; 1.1739x over previous
#include <cuda_runtime.h>
#include <math.h>

typedef unsigned long long u64;
typedef unsigned int u32;

// ---------------------------------------------------------------- constants
#define D_MODEL 512
#define D_INNER 512
#define D_STATE 16
#define DT_RANK 32
#define BB      4
#define LL      2048
#define MTOK    (BB*LL)       // 8192 tokens
#define CH_T    64            // scan chunk length
#define NCHUNK  (LL/CH_T)     // 32 chunks

// ---------------------------------------------------------------- scratch
__device__ __align__(16) float g_hstats[BB*D_MODEL];
__device__ __align__(16) float g_h    [MTOK*D_MODEL];
__device__ __align__(16) float g_xn   [MTOK*D_MODEL];
__device__ __align__(16) float g_xz   [MTOK*2*D_INNER];
__device__ __align__(16) float g_u    [MTOK*D_INNER];
__device__ __align__(16) float g_xdbc [MTOK*64];
__device__ __align__(16) float g_delta[MTOK*D_INNER];
__device__ __align__(16) float g_q    [BB*D_INNER*NCHUNK*D_STATE];
__device__ __align__(16) float g_dsum [BB*D_INNER*NCHUNK];
__device__ __align__(16) float g_hinit[BB*D_INNER*NCHUNK*D_STATE];
__device__ __align__(16) float g_y    [MTOK*D_INNER];

// ---------------------------------------------------------------- tf32 helpers
__device__ __forceinline__ u32 f2tf32(float f) {
    u32 r;
    asm("cvt.rna.tf32.f32 %0, %1;" : "=r"(r) : "f"(f));
    return r;
}
__device__ __forceinline__ void mma_tf32_v(float* d, u32 a0, u32 a1, u32 a2, u32 a3,
                                           u32 b0, u32 b1) {
    asm volatile(
        "mma.sync.aligned.m16n8k8.row.col.f32.tf32.tf32.f32 "
        "{%0,%1,%2,%3}, {%4,%5,%6,%7}, {%8,%9}, {%0,%1,%2,%3};"
        : "+f"(d[0]), "+f"(d[1]), "+f"(d[2]), "+f"(d[3])
        : "r"(a0), "r"(a1), "r"(a2), "r"(a3), "r"(b0), "r"(b1));
}

// ---------------------------------------------------------------- TF32 GEMM (NT)
// C[M,N] = A[M,K] @ B[N,K]^T ; tf32 inputs, fp32 accumulate.
// Block 128x128, BK=32, 256 threads = 8 warps (4 M x 2 N), warp tile 32x64.
// Smem stores k permuted: col perm(k) = (k&3)*8 + (k>>2). A thread's 8 needed
// k-values (stride 4) are then contiguous -> uint4 fragment loads (LDS.128).
// __launch_bounds__(256, 2): cap regs at 128 so 2 CTAs/SM stay resident
// (R9 showed 139 regs -> 1 CTA/SM -> occupancy cliff -> regression).
// EPI: 0 = none, 1 = relu(acc + bias[(m>>11)*512 + n])
template<int EPI>
__global__ __launch_bounds__(256, 2)
void tf32gemm_nt(const float* __restrict__ A, const float* __restrict__ B,
                 float* __restrict__ C, int M, int N, int K,
                 int lda, int ldb, int ldc, const float* __restrict__ bias)
{
    constexpr int BM = 128, BN = 128, BK = 32, LDS_S = BK + 4;  // pad->conflict-free reads
    __shared__ u32 As[BM][LDS_S];
    __shared__ u32 Bs[BN][LDS_S];

    const int tid  = threadIdx.x;
    const int lane = tid & 31;
    const int warp = tid >> 5;
    const int gid  = lane >> 2;      // 0..7
    const int tig  = lane & 3;       // 0..3
    const int wm   = warp & 3;       // 4 warps along M
    const int wn   = warp >> 2;      // 2 warps along N
    const int m0   = blockIdx.y * BM;
    const int n0   = blockIdx.x * BN;

    float acc[2][8][4];
#pragma unroll
    for (int i = 0; i < 2; i++)
#pragma unroll
        for (int j = 0; j < 8; j++)
#pragma unroll
            for (int r = 0; r < 4; r++) acc[i][j][r] = 0.f;

    // tile loader: 128 rows x 32 k; each thread: float4 at k-offset lc, 4 row-passes
    const int lr = tid >> 3;         // row within pass
    const int lc = (tid & 7) * 4;    // k offset (consecutive 4 k)
    const int lq = tid & 7;          // = lc>>2 : permuted sub-column

    for (int k0 = 0; k0 < K; k0 += BK) {
#pragma unroll
        for (int p = 0; p < 4; p++) {
            int r = lr + p * 32;
            float4 va = *(const float4*)(A + (size_t)(m0 + r) * lda + k0 + lc);
            As[r][lq     ] = f2tf32(va.x);   // k = lc+0 -> col 0*8 + q
            As[r][lq + 8 ] = f2tf32(va.y);   // k = lc+1 -> col 8 + q
            As[r][lq + 16] = f2tf32(va.z);
            As[r][lq + 24] = f2tf32(va.w);
            float4 vb = *(const float4*)(B + (size_t)(n0 + r) * ldb + k0 + lc);
            Bs[r][lq     ] = f2tf32(vb.x);
            Bs[r][lq + 8 ] = f2tf32(vb.y);
            Bs[r][lq + 16] = f2tf32(vb.z);
            Bs[r][lq + 24] = f2tf32(vb.w);
        }
        __syncthreads();

        // two half-BK groups; each uint4 covers 2 k-atoms (even: .x/.y, odd: .z/.w)
#pragma unroll
        for (int kg = 0; kg < 2; kg++) {
            const int fc = tig * 8 + kg * 4;     // fragment column
            u32 ae[2][4], ao[2][4];
#pragma unroll
            for (int i = 0; i < 2; i++) {
                const int mr = wm * 32 + i * 16;
                uint4 lo = *(const uint4*)&As[mr + gid    ][fc];
                uint4 hi = *(const uint4*)&As[mr + gid + 8][fc];
                ae[i][0] = lo.x; ae[i][1] = hi.x; ae[i][2] = lo.y; ae[i][3] = hi.y;
                ao[i][0] = lo.z; ao[i][1] = hi.z; ao[i][2] = lo.w; ao[i][3] = hi.w;
            }
#pragma unroll
            for (int j = 0; j < 8; j++) {
                const int nr = wn * 64 + j * 8;
                uint4 vb = *(const uint4*)&Bs[nr + gid][fc];
                mma_tf32_v(acc[0][j], ae[0][0], ae[0][1], ae[0][2], ae[0][3], vb.x, vb.y);
                mma_tf32_v(acc[1][j], ae[1][0], ae[1][1], ae[1][2], ae[1][3], vb.x, vb.y);
                mma_tf32_v(acc[0][j], ao[0][0], ao[0][1], ao[0][2], ao[0][3], vb.z, vb.w);
                mma_tf32_v(acc[1][j], ao[1][0], ao[1][1], ao[1][2], ao[1][3], vb.z, vb.w);
            }
        }
        __syncthreads();
    }

    // epilogue: c0=(gid, 2t), c1=(gid, 2t+1), c2=(gid+8, 2t), c3=(gid+8, 2t+1)
#pragma unroll
    for (int i = 0; i < 2; i++) {
        const int mlo = m0 + wm * 32 + i * 16 + gid;
        const int mhi = mlo + 8;
#pragma unroll
        for (int j = 0; j < 8; j++) {
            const int n = n0 + wn * 64 + j * 8 + tig * 2;
            float2 f01 = make_float2(acc[i][j][0], acc[i][j][1]);
            float2 f23 = make_float2(acc[i][j][2], acc[i][j][3]);
            if (EPI == 1) {
                const float* blo = bias + (mlo >> 11) * D_MODEL;
                const float* bhi = bias + (mhi >> 11) * D_MODEL;
                f01.x = fmaxf(f01.x + blo[n], 0.f); f01.y = fmaxf(f01.y + blo[n + 1], 0.f);
                f23.x = fmaxf(f23.x + bhi[n], 0.f); f23.y = fmaxf(f23.y + bhi[n + 1], 0.f);
            }
            *(float2*)&C[(size_t)mlo * ldc + n] = f01;
            *(float2*)&C[(size_t)mhi * ldc + n] = f23;
        }
    }
}

// ---------------------------------------------------------------- fp32 SGEMM (NT) for small GEMMs
template<int BM, int BN, int TM, int TN, int EPI>
__global__ __launch_bounds__(256)
void sgemm_nt(const float* __restrict__ A, const float* __restrict__ B,
              float* __restrict__ C, int M, int N, int K,
              int lda, int ldb, int ldc, const float* __restrict__ bias)
{
    constexpr int BK = 16;
    __shared__ float As[BK][BM + 4];
    __shared__ float Bs[BK][BN + 4];

    const int tid = threadIdx.x;
    const int tx  = tid & 15;
    const int ty  = tid >> 4;
    const int m0  = blockIdx.y * BM;
    const int n0  = blockIdx.x * BN;

    float acc[TM][TN];
#pragma unroll
    for (int i = 0; i < TM; i++)
#pragma unroll
        for (int j = 0; j < TN; j++) acc[i][j] = 0.f;

    const float* Ab = A + (size_t)m0 * lda;
    const float* Bb = B + (size_t)n0 * ldb;

    for (int k0 = 0; k0 < K; k0 += BK) {
#pragma unroll
        for (int i = 0; i < (BM * BK) / 1024; i++) {
            int t = tid + i * 256;
            int r = t >> 2, cq = t & 3;
            float4 v = *(const float4*)(Ab + (size_t)r * lda + k0 + cq * 4);
            As[cq*4+0][r] = v.x; As[cq*4+1][r] = v.y;
            As[cq*4+2][r] = v.z; As[cq*4+3][r] = v.w;
        }
#pragma unroll
        for (int i = 0; i < (BN * BK) / 1024; i++) {
            int t = tid + i * 256;
            int r = t >> 2, cq = t & 3;
            float4 v = *(const float4*)(Bb + (size_t)r * ldb + k0 + cq * 4);
            Bs[cq*4+0][r] = v.x; Bs[cq*4+1][r] = v.y;
            Bs[cq*4+2][r] = v.z; Bs[cq*4+3][r] = v.w;
        }
        __syncthreads();

#pragma unroll
        for (int k = 0; k < BK; k++) {
            float a[TM], b[TN];
#pragma unroll
            for (int i = 0; i < TM; i += 4) {
                float4 v = *(const float4*)&As[k][ty * TM + i];
                a[i] = v.x; a[i+1] = v.y; a[i+2] = v.z; a[i+3] = v.w;
            }
#pragma unroll
            for (int j = 0; j < TN; j += 4) {
                float4 v = *(const float4*)&Bs[k][tx * TN + j];
                b[j] = v.x; b[j+1] = v.y; b[j+2] = v.z; b[j+3] = v.w;
            }
#pragma unroll
            for (int i = 0; i < TM; i++)
#pragma unroll
                for (int j = 0; j < TN; j++)
                    acc[i][j] = fmaf(a[i], b[j], acc[i][j]);
        }
        __syncthreads();
    }

#pragma unroll
    for (int i = 0; i < TM; i++) {
        int m = m0 + ty * TM + i;
#pragma unroll
        for (int j = 0; j < TN; j++) {
            int n = n0 + tx * TN + j;
            float v = acc[i][j];
            if (EPI == 2) {          // dt_proj: + bias, softplus
                v += bias[n];
                v = (v > 20.f) ? v : log1pf(expf(v));
            }
            C[(size_t)m * ldc + n] = v;
        }
    }
}

// ---------------------------------------------------------------- hstats
__global__ void hstats_kernel(const float* __restrict__ gW1,
                              const float* __restrict__ gb1,
                              const float* __restrict__ xstat)
{
    int idx = blockIdx.x * blockDim.x + threadIdx.x;
    if (idx >= BB * D_MODEL) return;
    int b = idx >> 9, j = idx & 511;
    const float* w  = gW1 + (size_t)j * (2 * D_MODEL) + D_MODEL;
    const float* xs = xstat + b * D_MODEL;
    float s = gb1[j];
#pragma unroll 8
    for (int k = 0; k < D_MODEL; k++) s = fmaf(w[k], xs[k], s);
    g_hstats[idx] = s;
}

// ---------------------------------------------------------------- gate + LN
__global__ __launch_bounds__(256)
void gate_ln_kernel(const float* __restrict__ xsig, const float* __restrict__ xstat,
                    const float* __restrict__ h,    const float* __restrict__ gW2,
                    const float* __restrict__ gb2,  const float* __restrict__ lng,
                    const float* __restrict__ lnb,  float* __restrict__ xn)
{
    const int t = blockIdx.x;
    const int b = t >> 11;
    const int tid = threadIdx.x;
    const int d0 = tid, d1 = tid + 256;

    __shared__ float sred[8];
    __shared__ float sred2[8][2];
    __shared__ float sbc[2];

    const float* hr = h + (size_t)t * D_MODEL;
    float p = hr[d0] * gW2[d0] + hr[d1] * gW2[d1];
#pragma unroll
    for (int o = 16; o > 0; o >>= 1) p += __shfl_xor_sync(0xffffffffu, p, o);
    if ((tid & 31) == 0) sred[tid >> 5] = p;
    __syncthreads();
    if (tid == 0) {
        float s = 0.f;
        for (int w = 0; w < 8; w++) s += sred[w];
        sbc[0] = 1.f / (1.f + expf(-(s + gb2[0])));
    }
    __syncthreads();
    const float gate = sbc[0];

    float x0 = xsig[(size_t)t * D_MODEL + d0] + gate * xstat[b * D_MODEL + d0];
    float x1 = xsig[(size_t)t * D_MODEL + d1] + gate * xstat[b * D_MODEL + d1];
    float s  = x0 + x1;
    float ss = x0 * x0 + x1 * x1;
#pragma unroll
    for (int o = 16; o > 0; o >>= 1) {
        s  += __shfl_xor_sync(0xffffffffu, s,  o);
        ss += __shfl_xor_sync(0xffffffffu, ss, o);
    }
    if ((tid & 31) == 0) { sred2[tid >> 5][0] = s; sred2[tid >> 5][1] = ss; }
    __syncthreads();
    if (tid == 0) {
        float S = 0.f, SS = 0.f;
        for (int w = 0; w < 8; w++) { S += sred2[w][0]; SS += sred2[w][1]; }
        float mu  = S * (1.f / D_MODEL);
        float var = SS * (1.f / D_MODEL) - mu * mu;
        sbc[0] = mu;
        sbc[1] = rsqrtf(var + 1e-5f);
    }
    __syncthreads();
    const float mu = sbc[0], rstd = sbc[1];
    xn[(size_t)t * D_MODEL + d0] = (x0 - mu) * rstd * lng[d0] + lnb[d0];
    xn[(size_t)t * D_MODEL + d1] = (x1 - mu) * rstd * lng[d1] + lnb[d1];
}

// ---------------------------------------------------------------- conv(k=2)+silu
__global__ void conv_silu_kernel(const float* __restrict__ xz,
                                 const float* __restrict__ conv_w,
                                 const float* __restrict__ conv_b,
                                 float* __restrict__ u)
{
    int idx = blockIdx.x * blockDim.x + threadIdx.x;
    if (idx >= MTOK * D_INNER) return;
    int d = idx & 511;
    int l = (idx >> 9) & (LL - 1);
    int t = idx >> 9;
    float ucur  = xz[(size_t)t * (2 * D_INNER) + d];
    float uprev = (l > 0) ? xz[(size_t)(t - 1) * (2 * D_INNER) + d] : 0.f;
    float v = conv_b[d] + conv_w[d * 2 + 0] * uprev + conv_w[d * 2 + 1] * ucur;
    float sg = 1.f / (1.f + __expf(-v));
    u[idx] = v * sg;
}

// ---------------------------------------------------------------- scan helpers
__device__ __forceinline__ bool load_aexp(const float* __restrict__ A_log,
                                          int d, float* aexp)
{
    bool fast = true;
#pragma unroll
    for (int n = 0; n < D_STATE; n++) {
        aexp[n] = expf(A_log[d * D_STATE + n]);
        if (fabsf(aexp[n] - (float)(n + 1)) > 1e-2f) fast = false;
    }
    return fast;
}

// ---- pass 1
__global__ __launch_bounds__(128)
void scan_c1(const float* __restrict__ xdbc, const float* __restrict__ delta,
             const float* __restrict__ u,    const float* __restrict__ A_log)
{
    const int d = blockIdx.x * 128 + threadIdx.x;
    const int c = blockIdx.y, b = blockIdx.z;

    __shared__ float sB[CH_T * D_STATE];
    for (int i = threadIdx.x; i < CH_T * D_STATE; i += 128) {
        int j = i >> 4, n = i & 15;
        sB[i] = xdbc[(size_t)(b * LL + c * CH_T + j) * 64 + DT_RANK + n];
    }
    __syncthreads();

    float aexp[D_STATE];
    const bool fast = load_aexp(A_log, d, aexp);

    float h[D_STATE];
#pragma unroll
    for (int n = 0; n < D_STATE; n++) h[n] = 0.f;
    float dsum = 0.f;

    const float* dp = delta + (size_t)(b * LL + c * CH_T) * D_INNER + d;
    const float* up = u     + (size_t)(b * LL + c * CH_T) * D_INNER + d;

    if (fast) {
        for (int j = 0; j < CH_T; j++) {
            float de = dp[j * D_INNER], uu = up[j * D_INNER];
            dsum += de;
            float du = de * uu;
            float r = __expf(-de), rp = r;
#pragma unroll
            for (int n = 0; n < D_STATE; n++) {
                h[n] = fmaf(rp, h[n], du * sB[j * D_STATE + n]);
                rp *= r;
            }
        }
    } else {
        for (int j = 0; j < CH_T; j++) {
            float de = dp[j * D_INNER], uu = up[j * D_INNER];
            dsum += de;
            float du = de * uu;
#pragma unroll
            for (int n = 0; n < D_STATE; n++)
                h[n] = fmaf(__expf(-de * aexp[n]), h[n], du * sB[j * D_STATE + n]);
        }
    }

    const size_t base = (size_t)(b * D_INNER + d) * NCHUNK + c;
#pragma unroll
    for (int n = 0; n < D_STATE; n++) g_q[base * D_STATE + n] = h[n];
    g_dsum[base] = dsum;
}

// ---- pass 2
__global__ void scan_c2(const float* __restrict__ A_log)
{
    int bd = blockIdx.x * blockDim.x + threadIdx.x;
    if (bd >= BB * D_INNER) return;
    int d = bd & 511;

    float aexp[D_STATE];
    const bool fast = load_aexp(A_log, d, aexp);

    float h[D_STATE];
#pragma unroll
    for (int n = 0; n < D_STATE; n++) h[n] = 0.f;

    for (int c = 0; c < NCHUNK; c++) {
        const size_t base = (size_t)bd * NCHUNK + c;
#pragma unroll
        for (int n = 0; n < D_STATE; n++) g_hinit[base * D_STATE + n] = h[n];
        float ds = g_dsum[base];
        if (fast) {
            float r = __expf(-ds), rp = r;
#pragma unroll
            for (int n = 0; n < D_STATE; n++) {
                h[n] = fmaf(rp, h[n], g_q[base * D_STATE + n]);
                rp *= r;
            }
        } else {
#pragma unroll
            for (int n = 0; n < D_STATE; n++)
                h[n] = fmaf(__expf(-ds * aexp[n]), h[n], g_q[base * D_STATE + n]);
        }
    }
}

// ---- pass 3
__global__ __launch_bounds__(128)
void scan_c3(const float* __restrict__ xdbc, const float* __restrict__ delta,
             const float* __restrict__ u,    const float* __restrict__ A_log,
             const float* __restrict__ Dp,   const float* __restrict__ xz,
             float* __restrict__ y)
{
    const int d = blockIdx.x * 128 + threadIdx.x;
    const int c = blockIdx.y, b = blockIdx.z;

    __shared__ float sB[CH_T * D_STATE];
    __shared__ float sC[CH_T * D_STATE];
    for (int i = threadIdx.x; i < CH_T * D_STATE; i += 128) {
        int j = i >> 4, n = i & 15;
        const float* row = xdbc + (size_t)(b * LL + c * CH_T + j) * 64;
        sB[i] = row[DT_RANK + n];
        sC[i] = row[DT_RANK + D_STATE + n];
    }
    __syncthreads();

    float aexp[D_STATE];
    const bool fast = load_aexp(A_log, d, aexp);

    const size_t base = (size_t)(b * D_INNER + d) * NCHUNK + c;
    float h[D_STATE];
#pragma unroll
    for (int n = 0; n < D_STATE; n++) h[n] = g_hinit[base * D_STATE + n];

    const float dpd = Dp[d];
    const float* dptr = delta + (size_t)(b * LL + c * CH_T) * D_INNER + d;
    const float* uptr = u     + (size_t)(b * LL + c * CH_T) * D_INNER + d;

    for (int j = 0; j < CH_T; j++) {
        float de = dptr[j * D_INNER], uu = uptr[j * D_INNER];
        float du = de * uu;
        float yv = 0.f;
        if (fast) {
            float r = __expf(-de), rp = r;
#pragma unroll
            for (int n = 0; n < D_STATE; n++) {
                h[n] = fmaf(rp, h[n], du * sB[j * D_STATE + n]);
                yv   = fmaf(h[n], sC[j * D_STATE + n], yv);
                rp *= r;
            }
        } else {
#pragma unroll
            for (int n = 0; n < D_STATE; n++) {
                h[n] = fmaf(__expf(-de * aexp[n]), h[n], du * sB[j * D_STATE + n]);
                yv   = fmaf(h[n], sC[j * D_STATE + n], yv);
            }
        }
        const int l = b * LL + c * CH_T + j;
        float z  = xz[(size_t)l * (2 * D_INNER) + D_INNER + d];
        float sg = 1.f / (1.f + __expf(-z));
        y[(size_t)l * D_INNER + d] = (yv + dpd * uu) * (z * sg);
    }
}

// ---------------------------------------------------------------- launch
static float* symaddr(const void* sym)
{
    void* p = nullptr;
    cudaGetSymbolAddress(&p, sym);
    return (float*)p;
}

extern "C" void kernel_launch(void* const* d_in, const int* in_sizes, int n_in,
                              void* d_out, int out_size)
{
    const float* x_signal  = (const float*)d_in[0];
    const float* x_stats   = (const float*)d_in[1];
    const float* gW1       = (const float*)d_in[2];
    const float* gb1       = (const float*)d_in[3];
    const float* gW2       = (const float*)d_in[4];
    const float* gb2       = (const float*)d_in[5];
    const float* ln_g      = (const float*)d_in[6];
    const float* ln_b      = (const float*)d_in[7];
    const float* in_proj_W = (const float*)d_in[8];
    const float* conv_w    = (const float*)d_in[9];
    const float* conv_b    = (const float*)d_in[10];
    const float* x_proj_W  = (const float*)d_in[11];
    const float* dt_proj_W = (const float*)d_in[12];
    const float* dt_proj_b = (const float*)d_in[13];
    const float* A_log     = (const float*)d_in[14];
    const float* Dp        = (const float*)d_in[15];
    const float* out_proj_W= (const float*)d_in[16];
    float* out = (float*)d_out;

    float* p_hstats = symaddr(g_hstats);
    float* p_h      = symaddr(g_h);
    float* p_xn     = symaddr(g_xn);
    float* p_xz     = symaddr(g_xz);
    float* p_u      = symaddr(g_u);
    float* p_xdbc   = symaddr(g_xdbc);
    float* p_delta  = symaddr(g_delta);
    float* p_y      = symaddr(g_y);

    const int M = MTOK;

    // 1) per-batch half of the gate MLP (x_stats is broadcast over L)
    hstats_kernel<<<8, 256>>>(gW1, gb1, x_stats);

    // 2) GEMM1 (tf32): H = relu(X @ W1a^T + hstats[b])
    tf32gemm_nt<1><<<dim3(D_MODEL/128, M/128), 256>>>(
        x_signal, gW1, p_h, M, D_MODEL, D_MODEL, D_MODEL, 2*D_MODEL, D_MODEL, p_hstats);

    // 3) gate scalar + residual + LayerNorm
    gate_ln_kernel<<<M, 256>>>(x_signal, x_stats, p_h, gW2, gb2, ln_g, ln_b, p_xn);

    // 4) GEMM2 (tf32): XZ = XN @ in_proj_W^T   (N = 1024)
    tf32gemm_nt<0><<<dim3(1024/128, M/128), 256>>>(
        p_xn, in_proj_W, p_xz, M, 2*D_INNER, D_MODEL, D_MODEL, D_MODEL, 2*D_INNER, nullptr);

    // 5) causal conv (k=2) + silu -> u
    conv_silu_kernel<<<(M*D_INNER)/256, 256>>>(p_xz, conv_w, conv_b, p_u);

    // 6) GEMM3 (fp32): XDBC = U @ x_proj_W^T   (N = 64)
    sgemm_nt<64,64,4,4,0><<<dim3(1, M/64), 256>>>(
        p_u, x_proj_W, p_xdbc, M, 64, D_INNER, D_INNER, D_INNER, 64, nullptr);

    // 7) GEMM4 (fp32): delta = softplus(XDBC[:, :32] @ dt_proj_W^T + dt_bias)
    sgemm_nt<128,128,8,8,2><<<dim3(D_INNER/128, M/128), 256>>>(
        p_xdbc, dt_proj_W, p_delta, M, D_INNER, DT_RANK, 64, DT_RANK, D_INNER, dt_proj_b);

    // 8-10) chunked selective scan
    scan_c1<<<dim3(D_INNER/128, NCHUNK, BB), 128>>>(p_xdbc, p_delta, p_u, A_log);
    scan_c2<<<16, 128>>>(A_log);
    scan_c3<<<dim3(D_INNER/128, NCHUNK, BB), 128>>>(p_xdbc, p_delta, p_u, A_log, Dp, p_xz, p_y);

    // 11) GEMM5 (tf32): out = Y @ out_proj_W^T
    tf32gemm_nt<0><<<dim3(D_MODEL/128, M/128), 256>>>(
        p_y, out_proj_W, out, M, D_MODEL, D_INNER, D_INNER, D_INNER, D_MODEL, nullptr);
}

// round 16
// speedup vs baseline: 1.2448x; 1.0604x over previous
#include <cuda_runtime.h>
#include <math.h>

typedef unsigned long long u64;
typedef unsigned int u32;

// ---------------------------------------------------------------- constants
#define D_MODEL 512
#define D_INNER 512
#define D_STATE 16
#define DT_RANK 32
#define BB      4
#define LL      2048
#define MTOK    (BB*LL)       // 8192 tokens
#define CH_T    64            // scan chunk length
#define NCHUNK  (LL/CH_T)     // 32 chunks

// ---------------------------------------------------------------- scratch
__device__ __align__(16) float g_hstats[BB*D_MODEL];
__device__ __align__(16) float g_h    [MTOK*D_MODEL];
__device__ __align__(16) u32   g_xn   [MTOK*D_MODEL];        // tf32 bits (GEMM2 A)
__device__ __align__(16) float g_xz   [MTOK*2*D_INNER];
__device__ __align__(16) float g_u    [MTOK*D_INNER];
__device__ __align__(16) float g_xdbc [MTOK*64];
__device__ __align__(16) float g_delta[MTOK*D_INNER];
__device__ __align__(16) float g_q    [BB*D_INNER*NCHUNK*D_STATE];
__device__ __align__(16) float g_dsum [BB*D_INNER*NCHUNK];
__device__ __align__(16) float g_hinit[BB*D_INNER*NCHUNK*D_STATE];
__device__ __align__(16) u32   g_y    [MTOK*D_INNER];        // tf32 bits (GEMM5 A)
__device__ __align__(16) u32   g_xs32 [MTOK*D_MODEL];        // tf32 x_signal (GEMM1 A)
__device__ __align__(16) u32   g_w1c  [D_MODEL*2*D_MODEL];   // tf32 gW1 (GEMM1 B)
__device__ __align__(16) u32   g_inWc [2*D_INNER*D_MODEL];   // tf32 in_proj_W
__device__ __align__(16) u32   g_outWc[D_MODEL*D_INNER];     // tf32 out_proj_W

// ---------------------------------------------------------------- tf32 helpers
__device__ __forceinline__ u32 f2tf32(float f) {
    u32 r;
    asm("cvt.rna.tf32.f32 %0, %1;" : "=r"(r) : "f"(f));
    return r;
}
__device__ __forceinline__ void mma_tf32_v(float* d, u32 a0, u32 a1, u32 a2, u32 a3,
                                           u32 b0, u32 b1) {
    asm volatile(
        "mma.sync.aligned.m16n8k8.row.col.f32.tf32.tf32.f32 "
        "{%0,%1,%2,%3}, {%4,%5,%6,%7}, {%8,%9}, {%0,%1,%2,%3};"
        : "+f"(d[0]), "+f"(d[1]), "+f"(d[2]), "+f"(d[3])
        : "r"(a0), "r"(a1), "r"(a2), "r"(a3), "r"(b0), "r"(b1));
}
__device__ __forceinline__ void cp16(const u32* smem_ptr, const u32* g) {
    u32 sa = (u32)__cvta_generic_to_shared(smem_ptr);
    asm volatile("cp.async.cg.shared.global [%0], [%1], 16;" :: "r"(sa), "l"(g));
}

// ---------------------------------------------------------------- elementwise tf32 convert
__global__ void cvt_tf32_kernel(const float* __restrict__ in, u32* __restrict__ out, int n4)
{
    int i = blockIdx.x * blockDim.x + threadIdx.x;
    if (i >= n4) return;
    float4 v = ((const float4*)in)[i];
    uint4 o;
    o.x = f2tf32(v.x); o.y = f2tf32(v.y); o.z = f2tf32(v.z); o.w = f2tf32(v.w);
    ((uint4*)out)[i] = o;
}

// ---------------------------------------------------------------- TF32 GEMM (NT), cp.async double-buffered
// C[M,N] = A[M,K] @ B[N,K]^T ; A,B pre-converted tf32 bits; fp32 accumulate.
// Block 128x128, BK=32, 256 threads = 8 warps (4 M x 2 N), warp tile 32x64.
// Smem layout + fragment mapping IDENTICAL to proven R6 kernel; only the feed
// changes: LDGSTS 16B chunks into 2-stage ring, overlapping loads with MMA.
// EPI: 0 = none, 1 = relu(acc + bias[(m>>11)*512 + n])
template<int EPI>
__global__ __launch_bounds__(256, 2)
void tf32gemm_cp(const u32* __restrict__ A, const u32* __restrict__ B,
                 float* __restrict__ C, int M, int N, int K,
                 int lda, int ldb, int ldc, const float* __restrict__ bias)
{
    constexpr int BM = 128, BN = 128, BK = 32, LDS_S = BK + 4;
    constexpr int STAGE = (BM + BN) * LDS_S;      // u32 per stage (A then B)
    extern __shared__ u32 sm[];

    const int tid  = threadIdx.x;
    const int lane = tid & 31;
    const int warp = tid >> 5;
    const int gid  = lane >> 2;
    const int tig  = lane & 3;
    const int wm   = warp & 3;
    const int wn   = warp >> 2;
    const int m0   = blockIdx.y * BM;
    const int n0   = blockIdx.x * BN;

    float acc[2][8][4];
#pragma unroll
    for (int i = 0; i < 2; i++)
#pragma unroll
        for (int j = 0; j < 8; j++)
#pragma unroll
            for (int r = 0; r < 4; r++) acc[i][j][r] = 0.f;

    const int lr = tid >> 3;         // row within 32-row pass
    const int lc = (tid & 7) * 4;    // k offset (16B chunk)

    const u32* Ag = A + (size_t)m0 * lda + lc;
    const u32* Bg = B + (size_t)n0 * ldb + lc;

#define FILL(s, k0)                                                        \
    {                                                                      \
        u32* dstA = sm + (s) * STAGE;                                      \
        u32* dstB = sm + (s) * STAGE + BM * LDS_S;                         \
        _Pragma("unroll")                                                  \
        for (int p = 0; p < 4; p++) {                                      \
            int r = lr + p * 32;                                           \
            cp16(dstA + r * LDS_S + lc, Ag + (size_t)r * lda + (k0));      \
            cp16(dstB + r * LDS_S + lc, Bg + (size_t)r * ldb + (k0));      \
        }                                                                  \
    }

    FILL(0, 0);
    asm volatile("cp.async.commit_group;");

    const int KT = K / BK;
    for (int kt = 0; kt < KT; kt++) {
        const int cur = kt & 1;
        if (kt + 1 < KT) FILL(cur ^ 1, (kt + 1) * BK);
        asm volatile("cp.async.commit_group;");
        asm volatile("cp.async.wait_group 1;");
        __syncthreads();

        const u32* Ac = sm + cur * STAGE;
        const u32* Bc = sm + cur * STAGE + BM * LDS_S;
#pragma unroll
        for (int ka = 0; ka < 4; ka++) {
            const int kk = ka * 8;
            u32 af[2][4];
#pragma unroll
            for (int i = 0; i < 2; i++) {
                const int mr = wm * 32 + i * 16;
                af[i][0] = Ac[(mr + gid    ) * LDS_S + kk + tig    ];
                af[i][1] = Ac[(mr + gid + 8) * LDS_S + kk + tig    ];
                af[i][2] = Ac[(mr + gid    ) * LDS_S + kk + tig + 4];
                af[i][3] = Ac[(mr + gid + 8) * LDS_S + kk + tig + 4];
            }
#pragma unroll
            for (int j = 0; j < 8; j++) {
                const int nr = wn * 64 + j * 8;
                u32 b0 = Bc[(nr + gid) * LDS_S + kk + tig    ];
                u32 b1 = Bc[(nr + gid) * LDS_S + kk + tig + 4];
                mma_tf32_v(acc[0][j], af[0][0], af[0][1], af[0][2], af[0][3], b0, b1);
                mma_tf32_v(acc[1][j], af[1][0], af[1][1], af[1][2], af[1][3], b0, b1);
            }
        }
        __syncthreads();
    }
#undef FILL

    // epilogue: c0=(gid, 2t), c1=(gid, 2t+1), c2=(gid+8, 2t), c3=(gid+8, 2t+1)
#pragma unroll
    for (int i = 0; i < 2; i++) {
        const int mlo = m0 + wm * 32 + i * 16 + gid;
        const int mhi = mlo + 8;
#pragma unroll
        for (int j = 0; j < 8; j++) {
            const int n = n0 + wn * 64 + j * 8 + tig * 2;
            float2 f01 = make_float2(acc[i][j][0], acc[i][j][1]);
            float2 f23 = make_float2(acc[i][j][2], acc[i][j][3]);
            if (EPI == 1) {
                const float* blo = bias + (mlo >> 11) * D_MODEL;
                const float* bhi = bias + (mhi >> 11) * D_MODEL;
                f01.x = fmaxf(f01.x + blo[n], 0.f); f01.y = fmaxf(f01.y + blo[n + 1], 0.f);
                f23.x = fmaxf(f23.x + bhi[n], 0.f); f23.y = fmaxf(f23.y + bhi[n + 1], 0.f);
            }
            *(float2*)&C[(size_t)mlo * ldc + n] = f01;
            *(float2*)&C[(size_t)mhi * ldc + n] = f23;
        }
    }
}

// ---------------------------------------------------------------- fp32 SGEMM (NT) for small GEMMs
template<int BM, int BN, int TM, int TN, int EPI>
__global__ __launch_bounds__(256)
void sgemm_nt(const float* __restrict__ A, const float* __restrict__ B,
              float* __restrict__ C, int M, int N, int K,
              int lda, int ldb, int ldc, const float* __restrict__ bias)
{
    constexpr int BK = 16;
    __shared__ float As[BK][BM + 4];
    __shared__ float Bs[BK][BN + 4];

    const int tid = threadIdx.x;
    const int tx  = tid & 15;
    const int ty  = tid >> 4;
    const int m0  = blockIdx.y * BM;
    const int n0  = blockIdx.x * BN;

    float acc[TM][TN];
#pragma unroll
    for (int i = 0; i < TM; i++)
#pragma unroll
        for (int j = 0; j < TN; j++) acc[i][j] = 0.f;

    const float* Ab = A + (size_t)m0 * lda;
    const float* Bb = B + (size_t)n0 * ldb;

    for (int k0 = 0; k0 < K; k0 += BK) {
#pragma unroll
        for (int i = 0; i < (BM * BK) / 1024; i++) {
            int t = tid + i * 256;
            int r = t >> 2, cq = t & 3;
            float4 v = *(const float4*)(Ab + (size_t)r * lda + k0 + cq * 4);
            As[cq*4+0][r] = v.x; As[cq*4+1][r] = v.y;
            As[cq*4+2][r] = v.z; As[cq*4+3][r] = v.w;
        }
#pragma unroll
        for (int i = 0; i < (BN * BK) / 1024; i++) {
            int t = tid + i * 256;
            int r = t >> 2, cq = t & 3;
            float4 v = *(const float4*)(Bb + (size_t)r * ldb + k0 + cq * 4);
            Bs[cq*4+0][r] = v.x; Bs[cq*4+1][r] = v.y;
            Bs[cq*4+2][r] = v.z; Bs[cq*4+3][r] = v.w;
        }
        __syncthreads();

#pragma unroll
        for (int k = 0; k < BK; k++) {
            float a[TM], b[TN];
#pragma unroll
            for (int i = 0; i < TM; i += 4) {
                float4 v = *(const float4*)&As[k][ty * TM + i];
                a[i] = v.x; a[i+1] = v.y; a[i+2] = v.z; a[i+3] = v.w;
            }
#pragma unroll
            for (int j = 0; j < TN; j += 4) {
                float4 v = *(const float4*)&Bs[k][tx * TN + j];
                b[j] = v.x; b[j+1] = v.y; b[j+2] = v.z; b[j+3] = v.w;
            }
#pragma unroll
            for (int i = 0; i < TM; i++)
#pragma unroll
                for (int j = 0; j < TN; j++)
                    acc[i][j] = fmaf(a[i], b[j], acc[i][j]);
        }
        __syncthreads();
    }

#pragma unroll
    for (int i = 0; i < TM; i++) {
        int m = m0 + ty * TM + i;
#pragma unroll
        for (int j = 0; j < TN; j++) {
            int n = n0 + tx * TN + j;
            float v = acc[i][j];
            if (EPI == 2) {          // dt_proj: + bias, softplus
                v += bias[n];
                v = (v > 20.f) ? v : log1pf(expf(v));
            }
            C[(size_t)m * ldc + n] = v;
        }
    }
}

// ---------------------------------------------------------------- hstats
__global__ void hstats_kernel(const float* __restrict__ gW1,
                              const float* __restrict__ gb1,
                              const float* __restrict__ xstat)
{
    int idx = blockIdx.x * blockDim.x + threadIdx.x;
    if (idx >= BB * D_MODEL) return;
    int b = idx >> 9, j = idx & 511;
    const float* w  = gW1 + (size_t)j * (2 * D_MODEL) + D_MODEL;
    const float* xs = xstat + b * D_MODEL;
    float s = gb1[j];
#pragma unroll 8
    for (int k = 0; k < D_MODEL; k++) s = fmaf(w[k], xs[k], s);
    g_hstats[idx] = s;
}

// ---------------------------------------------------------------- gate + LN (emits tf32 bits)
__global__ __launch_bounds__(256)
void gate_ln_kernel(const float* __restrict__ xsig, const float* __restrict__ xstat,
                    const float* __restrict__ h,    const float* __restrict__ gW2,
                    const float* __restrict__ gb2,  const float* __restrict__ lng,
                    const float* __restrict__ lnb,  u32* __restrict__ xn)
{
    const int t = blockIdx.x;
    const int b = t >> 11;
    const int tid = threadIdx.x;
    const int d0 = tid, d1 = tid + 256;

    __shared__ float sred[8];
    __shared__ float sred2[8][2];
    __shared__ float sbc[2];

    const float* hr = h + (size_t)t * D_MODEL;
    float p = hr[d0] * gW2[d0] + hr[d1] * gW2[d1];
#pragma unroll
    for (int o = 16; o > 0; o >>= 1) p += __shfl_xor_sync(0xffffffffu, p, o);
    if ((tid & 31) == 0) sred[tid >> 5] = p;
    __syncthreads();
    if (tid == 0) {
        float s = 0.f;
        for (int w = 0; w < 8; w++) s += sred[w];
        sbc[0] = 1.f / (1.f + expf(-(s + gb2[0])));
    }
    __syncthreads();
    const float gate = sbc[0];

    float x0 = xsig[(size_t)t * D_MODEL + d0] + gate * xstat[b * D_MODEL + d0];
    float x1 = xsig[(size_t)t * D_MODEL + d1] + gate * xstat[b * D_MODEL + d1];
    float s  = x0 + x1;
    float ss = x0 * x0 + x1 * x1;
#pragma unroll
    for (int o = 16; o > 0; o >>= 1) {
        s  += __shfl_xor_sync(0xffffffffu, s,  o);
        ss += __shfl_xor_sync(0xffffffffu, ss, o);
    }
    if ((tid & 31) == 0) { sred2[tid >> 5][0] = s; sred2[tid >> 5][1] = ss; }
    __syncthreads();
    if (tid == 0) {
        float S = 0.f, SS = 0.f;
        for (int w = 0; w < 8; w++) { S += sred2[w][0]; SS += sred2[w][1]; }
        float mu  = S * (1.f / D_MODEL);
        float var = SS * (1.f / D_MODEL) - mu * mu;
        sbc[0] = mu;
        sbc[1] = rsqrtf(var + 1e-5f);
    }
    __syncthreads();
    const float mu = sbc[0], rstd = sbc[1];
    xn[(size_t)t * D_MODEL + d0] = f2tf32((x0 - mu) * rstd * lng[d0] + lnb[d0]);
    xn[(size_t)t * D_MODEL + d1] = f2tf32((x1 - mu) * rstd * lng[d1] + lnb[d1]);
}

// ---------------------------------------------------------------- conv(k=2)+silu
__global__ void conv_silu_kernel(const float* __restrict__ xz,
                                 const float* __restrict__ conv_w,
                                 const float* __restrict__ conv_b,
                                 float* __restrict__ u)
{
    int idx = blockIdx.x * blockDim.x + threadIdx.x;
    if (idx >= MTOK * D_INNER) return;
    int d = idx & 511;
    int l = (idx >> 9) & (LL - 1);
    int t = idx >> 9;
    float ucur  = xz[(size_t)t * (2 * D_INNER) + d];
    float uprev = (l > 0) ? xz[(size_t)(t - 1) * (2 * D_INNER) + d] : 0.f;
    float v = conv_b[d] + conv_w[d * 2 + 0] * uprev + conv_w[d * 2 + 1] * ucur;
    float sg = 1.f / (1.f + __expf(-v));
    u[idx] = v * sg;
}

// ---------------------------------------------------------------- scan helpers
__device__ __forceinline__ bool load_aexp(const float* __restrict__ A_log,
                                          int d, float* aexp)
{
    bool fast = true;
#pragma unroll
    for (int n = 0; n < D_STATE; n++) {
        aexp[n] = expf(A_log[d * D_STATE + n]);
        if (fabsf(aexp[n] - (float)(n + 1)) > 1e-2f) fast = false;
    }
    return fast;
}

// ---- pass 1
__global__ __launch_bounds__(128)
void scan_c1(const float* __restrict__ xdbc, const float* __restrict__ delta,
             const float* __restrict__ u,    const float* __restrict__ A_log)
{
    const int d = blockIdx.x * 128 + threadIdx.x;
    const int c = blockIdx.y, b = blockIdx.z;

    __shared__ float sB[CH_T * D_STATE];
    for (int i = threadIdx.x; i < CH_T * D_STATE; i += 128) {
        int j = i >> 4, n = i & 15;
        sB[i] = xdbc[(size_t)(b * LL + c * CH_T + j) * 64 + DT_RANK + n];
    }
    __syncthreads();

    float aexp[D_STATE];
    const bool fast = load_aexp(A_log, d, aexp);

    float h[D_STATE];
#pragma unroll
    for (int n = 0; n < D_STATE; n++) h[n] = 0.f;
    float dsum = 0.f;

    const float* dp = delta + (size_t)(b * LL + c * CH_T) * D_INNER + d;
    const float* up = u     + (size_t)(b * LL + c * CH_T) * D_INNER + d;

    if (fast) {
        for (int j = 0; j < CH_T; j++) {
            float de = dp[j * D_INNER], uu = up[j * D_INNER];
            dsum += de;
            float du = de * uu;
            float r = __expf(-de), rp = r;
#pragma unroll
            for (int n = 0; n < D_STATE; n++) {
                h[n] = fmaf(rp, h[n], du * sB[j * D_STATE + n]);
                rp *= r;
            }
        }
    } else {
        for (int j = 0; j < CH_T; j++) {
            float de = dp[j * D_INNER], uu = up[j * D_INNER];
            dsum += de;
            float du = de * uu;
#pragma unroll
            for (int n = 0; n < D_STATE; n++)
                h[n] = fmaf(__expf(-de * aexp[n]), h[n], du * sB[j * D_STATE + n]);
        }
    }

    const size_t base = (size_t)(b * D_INNER + d) * NCHUNK + c;
#pragma unroll
    for (int n = 0; n < D_STATE; n++) g_q[base * D_STATE + n] = h[n];
    g_dsum[base] = dsum;
}

// ---- pass 2
__global__ void scan_c2(const float* __restrict__ A_log)
{
    int bd = blockIdx.x * blockDim.x + threadIdx.x;
    if (bd >= BB * D_INNER) return;
    int d = bd & 511;

    float aexp[D_STATE];
    const bool fast = load_aexp(A_log, d, aexp);

    float h[D_STATE];
#pragma unroll
    for (int n = 0; n < D_STATE; n++) h[n] = 0.f;

    for (int c = 0; c < NCHUNK; c++) {
        const size_t base = (size_t)bd * NCHUNK + c;
#pragma unroll
        for (int n = 0; n < D_STATE; n++) g_hinit[base * D_STATE + n] = h[n];
        float ds = g_dsum[base];
        if (fast) {
            float r = __expf(-ds), rp = r;
#pragma unroll
            for (int n = 0; n < D_STATE; n++) {
                h[n] = fmaf(rp, h[n], g_q[base * D_STATE + n]);
                rp *= r;
            }
        } else {
#pragma unroll
            for (int n = 0; n < D_STATE; n++)
                h[n] = fmaf(__expf(-ds * aexp[n]), h[n], g_q[base * D_STATE + n]);
        }
    }
}

// ---- pass 3 (emits y as tf32 bits for GEMM5)
__global__ __launch_bounds__(128)
void scan_c3(const float* __restrict__ xdbc, const float* __restrict__ delta,
             const float* __restrict__ u,    const float* __restrict__ A_log,
             const float* __restrict__ Dp,   const float* __restrict__ xz,
             u32* __restrict__ y)
{
    const int d = blockIdx.x * 128 + threadIdx.x;
    const int c = blockIdx.y, b = blockIdx.z;

    __shared__ float sB[CH_T * D_STATE];
    __shared__ float sC[CH_T * D_STATE];
    for (int i = threadIdx.x; i < CH_T * D_STATE; i += 128) {
        int j = i >> 4, n = i & 15;
        const float* row = xdbc + (size_t)(b * LL + c * CH_T + j) * 64;
        sB[i] = row[DT_RANK + n];
        sC[i] = row[DT_RANK + D_STATE + n];
    }
    __syncthreads();

    float aexp[D_STATE];
    const bool fast = load_aexp(A_log, d, aexp);

    const size_t base = (size_t)(b * D_INNER + d) * NCHUNK + c;
    float h[D_STATE];
#pragma unroll
    for (int n = 0; n < D_STATE; n++) h[n] = g_hinit[base * D_STATE + n];

    const float dpd = Dp[d];
    const float* dptr = delta + (size_t)(b * LL + c * CH_T) * D_INNER + d;
    const float* uptr = u     + (size_t)(b * LL + c * CH_T) * D_INNER + d;

    for (int j = 0; j < CH_T; j++) {
        float de = dptr[j * D_INNER], uu = uptr[j * D_INNER];
        float du = de * uu;
        float yv = 0.f;
        if (fast) {
            float r = __expf(-de), rp = r;
#pragma unroll
            for (int n = 0; n < D_STATE; n++) {
                h[n] = fmaf(rp, h[n], du * sB[j * D_STATE + n]);
                yv   = fmaf(h[n], sC[j * D_STATE + n], yv);
                rp *= r;
            }
        } else {
#pragma unroll
            for (int n = 0; n < D_STATE; n++) {
                h[n] = fmaf(__expf(-de * aexp[n]), h[n], du * sB[j * D_STATE + n]);
                yv   = fmaf(h[n], sC[j * D_STATE + n], yv);
            }
        }
        const int l = b * LL + c * CH_T + j;
        float z  = xz[(size_t)l * (2 * D_INNER) + D_INNER + d];
        float sg = 1.f / (1.f + __expf(-z));
        y[(size_t)l * D_INNER + d] = f2tf32((yv + dpd * uu) * (z * sg));
    }
}

// ---------------------------------------------------------------- launch
static float* symaddrf(const void* sym)
{
    void* p = nullptr;
    cudaGetSymbolAddress(&p, sym);
    return (float*)p;
}
static u32* symaddru(const void* sym)
{
    void* p = nullptr;
    cudaGetSymbolAddress(&p, sym);
    return (u32*)p;
}

extern "C" void kernel_launch(void* const* d_in, const int* in_sizes, int n_in,
                              void* d_out, int out_size)
{
    const float* x_signal  = (const float*)d_in[0];
    const float* x_stats   = (const float*)d_in[1];
    const float* gW1       = (const float*)d_in[2];
    const float* gb1       = (const float*)d_in[3];
    const float* gW2       = (const float*)d_in[4];
    const float* gb2       = (const float*)d_in[5];
    const float* ln_g      = (const float*)d_in[6];
    const float* ln_b      = (const float*)d_in[7];
    const float* in_proj_W = (const float*)d_in[8];
    const float* conv_w    = (const float*)d_in[9];
    const float* conv_b    = (const float*)d_in[10];
    const float* x_proj_W  = (const float*)d_in[11];
    const float* dt_proj_W = (const float*)d_in[12];
    const float* dt_proj_b = (const float*)d_in[13];
    const float* A_log     = (const float*)d_in[14];
    const float* Dp        = (const float*)d_in[15];
    const float* out_proj_W= (const float*)d_in[16];
    float* out = (float*)d_out;

    float* p_hstats = symaddrf(g_hstats);
    float* p_h      = symaddrf(g_h);
    u32*   p_xn     = symaddru(g_xn);
    float* p_xz     = symaddrf(g_xz);
    float* p_u      = symaddrf(g_u);
    float* p_xdbc   = symaddrf(g_xdbc);
    float* p_delta  = symaddrf(g_delta);
    u32*   p_y      = symaddru(g_y);
    u32*   p_xs32   = symaddru(g_xs32);
    u32*   p_w1c    = symaddru(g_w1c);
    u32*   p_inWc   = symaddru(g_inWc);
    u32*   p_outWc  = symaddru(g_outWc);

    const int M = MTOK;
    const int GEMM_SMEM = 2 * (256 * 36) * 4;   // 2 stages x (A+B rows) x 36 u32 = 73728 B

    cudaFuncSetAttribute(tf32gemm_cp<0>, cudaFuncAttributeMaxDynamicSharedMemorySize, GEMM_SMEM);
    cudaFuncSetAttribute(tf32gemm_cp<1>, cudaFuncAttributeMaxDynamicSharedMemorySize, GEMM_SMEM);

    // 0) tf32 pre-conversion of GEMM operands
    cvt_tf32_kernel<<<(MTOK*D_MODEL/4 + 255)/256, 256>>>(x_signal, p_xs32, MTOK*D_MODEL/4);
    cvt_tf32_kernel<<<(D_MODEL*2*D_MODEL/4 + 255)/256, 256>>>(gW1, p_w1c, D_MODEL*2*D_MODEL/4);
    cvt_tf32_kernel<<<(2*D_INNER*D_MODEL/4 + 255)/256, 256>>>(in_proj_W, p_inWc, 2*D_INNER*D_MODEL/4);
    cvt_tf32_kernel<<<(D_MODEL*D_INNER/4 + 255)/256, 256>>>(out_proj_W, p_outWc, D_MODEL*D_INNER/4);

    // 1) per-batch half of the gate MLP (x_stats is broadcast over L)
    hstats_kernel<<<8, 256>>>(gW1, gb1, x_stats);

    // 2) GEMM1 (tf32, cp.async): H = relu(X @ W1a^T + hstats[b])
    tf32gemm_cp<1><<<dim3(D_MODEL/128, M/128), 256, GEMM_SMEM>>>(
        p_xs32, p_w1c, p_h, M, D_MODEL, D_MODEL, D_MODEL, 2*D_MODEL, D_MODEL, p_hstats);

    // 3) gate scalar + residual + LayerNorm -> xn (tf32 bits)
    gate_ln_kernel<<<M, 256>>>(x_signal, x_stats, p_h, gW2, gb2, ln_g, ln_b, p_xn);

    // 4) GEMM2 (tf32, cp.async): XZ = XN @ in_proj_W^T   (N = 1024)
    tf32gemm_cp<0><<<dim3(1024/128, M/128), 256, GEMM_SMEM>>>(
        p_xn, p_inWc, p_xz, M, 2*D_INNER, D_MODEL, D_MODEL, D_MODEL, 2*D_INNER, nullptr);

    // 5) causal conv (k=2) + silu -> u
    conv_silu_kernel<<<(M*D_INNER)/256, 256>>>(p_xz, conv_w, conv_b, p_u);

    // 6) GEMM3 (fp32): XDBC = U @ x_proj_W^T   (N = 64)
    sgemm_nt<64,64,4,4,0><<<dim3(1, M/64), 256>>>(
        p_u, x_proj_W, p_xdbc, M, 64, D_INNER, D_INNER, D_INNER, 64, nullptr);

    // 7) GEMM4 (fp32): delta = softplus(XDBC[:, :32] @ dt_proj_W^T + dt_bias)
    sgemm_nt<128,128,8,8,2><<<dim3(D_INNER/128, M/128), 256>>>(
        p_xdbc, dt_proj_W, p_delta, M, D_INNER, DT_RANK, 64, DT_RANK, D_INNER, dt_proj_b);

    // 8-10) chunked selective scan
    scan_c1<<<dim3(D_INNER/128, NCHUNK, BB), 128>>>(p_xdbc, p_delta, p_u, A_log);
    scan_c2<<<16, 128>>>(A_log);
    scan_c3<<<dim3(D_INNER/128, NCHUNK, BB), 128>>>(p_xdbc, p_delta, p_u, A_log, Dp, p_xz, p_y);

    // 11) GEMM5 (tf32, cp.async): out = Y @ out_proj_W^T
    tf32gemm_cp<0><<<dim3(D_MODEL/128, M/128), 256, GEMM_SMEM>>>(
        p_y, p_outWc, out, M, D_MODEL, D_INNER, D_INNER, D_INNER, D_MODEL, nullptr);
}